// round 8
// baseline (speedup 1.0000x reference)
#include <cuda_runtime.h>
#include <cuda_bf16.h>
#include <cstdint>

// Problem constants
#define Bb 4
#define Tt 4096
#define Cc 1024
#define Hh 64
#define KPAD 68    // proj X smem stride (words)
#define WPAD 200   // proj W smem stride (words)
#define KVPAD 68   // attn K/V smem stride (words)
#define NCHUNK 16  // attn key-tiles per split chunk
#define LOG2E 1.44269504088896f

// Scratch for projected q/k/v (4 MB each)
__device__ float g_q[Bb * Tt * Hh];
__device__ float g_k[Bb * Tt * Hh];
__device__ float g_v[Bb * Tt * Hh];

// Split-K partials: slot = ((b*64+qt)*4 + ci)
__device__ float  g_pO[Bb * 64 * 4][64][Hh];
__device__ float2 g_pml[Bb * 64 * 4][64];

__device__ __forceinline__ uint32_t f2tf(float f) {
    uint32_t u; asm("cvt.rna.tf32.f32 %0, %1;" : "=r"(u) : "f"(f)); return u;
}
__device__ __forceinline__ float ex2(float f) {
    float r; asm("ex2.approx.f32 %0, %1;" : "=f"(r) : "f"(f)); return r;
}
__device__ __forceinline__ void cpa16(uint32_t dst, const void* src) {
    asm volatile("cp.async.ca.shared.global [%0], [%1], 16;" :: "r"(dst), "l"(src));
}
#define CP_COMMIT() asm volatile("cp.async.commit_group;")
#define CP_WAIT0()  asm volatile("cp.async.wait_group 0;")

__device__ __forceinline__ void mma_tf32(float* d, const uint32_t* a,
                                         uint32_t b0, uint32_t b1) {
    asm volatile(
        "mma.sync.aligned.m16n8k8.row.col.f32.tf32.tf32.f32 "
        "{%0,%1,%2,%3}, {%4,%5,%6,%7}, {%8,%9}, {%0,%1,%2,%3};"
        : "+f"(d[0]), "+f"(d[1]), "+f"(d[2]), "+f"(d[3])
        : "r"(a[0]), "r"(a[1]), "r"(a[2]), "r"(a[3]), "r"(b0), "r"(b1));
}

// ---------------------------------------------------------------------------
// Kernel 1: fused QKV projection via tf32 mma (R5 structure — measured 58.5us).
// q is scaled by (1/sqrt(H)) * log2(e) so attention runs in log2 domain.
// ---------------------------------------------------------------------------
__global__ __launch_bounds__(128, 3) void proj_kernel(
    const float* __restrict__ x,
    const float* __restrict__ wk,
    const float* __restrict__ wq,
    const float* __restrict__ wv)
{
    extern __shared__ uint32_t smp[];
    uint32_t* Xs = smp;                 // [m][c] tf32, stride KPAD
    uint32_t* Ws = smp + 64 * KPAD;     // [c][z*64+h] tf32, stride WPAD

    const int m0 = blockIdx.x * 64;
    const int tid = threadIdx.x;
    const int wid = tid >> 5;
    const int lane = tid & 31;
    const int gid = lane >> 2;
    const int tig = lane & 3;
    const int lc = tid & 15;
    const int lr = tid >> 4;

    float o[6][4][4];
    #pragma unroll
    for (int nt = 0; nt < 6; nt++)
        #pragma unroll
        for (int rb = 0; rb < 4; rb++)
            #pragma unroll
            for (int j = 0; j < 4; j++) o[nt][rb][j] = 0.f;

    for (int k0 = 0; k0 < Cc; k0 += 64) {
        #pragma unroll
        for (int p = 0; p < 8; p++) {
            const int row = p * 8 + lr;
            float4 xv = *(const float4*)&x[(size_t)(m0 + row) * Cc + k0 + lc * 4];
            uint32_t* xd = &Xs[row * KPAD + lc * 4];
            xd[0] = f2tf(xv.x); xd[1] = f2tf(xv.y); xd[2] = f2tf(xv.z); xd[3] = f2tf(xv.w);
        }
        #pragma unroll
        for (int z = 0; z < 3; z++) {
            const float* __restrict__ w = (z == 0) ? wk : ((z == 1) ? wq : wv);
            #pragma unroll
            for (int p = 0; p < 8; p++) {
                const int row = p * 8 + lr;
                float4 wv4 = *(const float4*)&w[(size_t)(k0 + row) * Hh + lc * 4];
                uint32_t* wd = &Ws[row * WPAD + z * 64 + lc * 4];
                wd[0] = f2tf(wv4.x); wd[1] = f2tf(wv4.y); wd[2] = f2tf(wv4.z); wd[3] = f2tf(wv4.w);
            }
        }
        __syncthreads();

        #pragma unroll
        for (int s8 = 0; s8 < 8; s8++) {
            uint32_t a[4][4];
            #pragma unroll
            for (int rb = 0; rb < 4; rb++) {
                const int ar = rb * 16 + gid;
                a[rb][0] = Xs[(ar    ) * KPAD + s8 * 8 + tig    ];
                a[rb][1] = Xs[(ar + 8) * KPAD + s8 * 8 + tig    ];
                a[rb][2] = Xs[(ar    ) * KPAD + s8 * 8 + tig + 4];
                a[rb][3] = Xs[(ar + 8) * KPAD + s8 * 8 + tig + 4];
            }
            #pragma unroll
            for (int nt = 0; nt < 6; nt++) {
                const int ntp = wid * 6 + nt;
                uint32_t b0 = Ws[(s8 * 8 + tig    ) * WPAD + ntp * 8 + gid];
                uint32_t b1 = Ws[(s8 * 8 + tig + 4) * WPAD + ntp * 8 + gid];
                #pragma unroll
                for (int rb = 0; rb < 4; rb++)
                    mma_tf32(o[nt][rb], a[rb], b0, b1);
            }
        }
        __syncthreads();
    }

    #pragma unroll
    for (int nt = 0; nt < 6; nt++) {
        const int ntp = wid * 6 + nt;
        const int z = ntp >> 3;
        float* __restrict__ outp = (z == 0) ? g_k : ((z == 1) ? g_q : g_v);
        const float scale = (z == 1) ? (0.125f * LOG2E) : 1.0f;
        const int hc = (ntp & 7) * 8 + tig * 2;
        #pragma unroll
        for (int rb = 0; rb < 4; rb++) {
            const int mr = m0 + rb * 16 + gid;
            *(float2*)&outp[(size_t)(mr    ) * Hh + hc] =
                make_float2(o[nt][rb][0] * scale, o[nt][rb][1] * scale);
            *(float2*)&outp[(size_t)(mr + 8) * Hh + hc] =
                make_float2(o[nt][rb][2] * scale, o[nt][rb][3] * scale);
        }
    }
}

// ---------------------------------------------------------------------------
// Kernel 2: split-K causal flash attention, tf32 mma, P in registers.
// cp.async double-buffered raw K/V + in-place tf32 convert pass
// (cvt stays OFF the mma operand path).  Softmax in log2 domain (ex2).
// ---------------------------------------------------------------------------
__global__ __launch_bounds__(128, 3) void attn_kernel(
    const float* __restrict__ bias,
    float* __restrict__ outp)
{
    extern __shared__ float smu[];
    const int ASTG = 2 * 64 * KVPAD;   // 8704 words per stage (K then V)

    const int b = blockIdx.x & 3;
    const int v = blockIdx.x >> 2;
    const int u = 159 - v;
    int qt, ci, nch;
    if (u < 16)      { qt = u;                 ci = 0;            nch = 1; }
    else if (u < 48) { int j = u - 16; qt = 16 + (j >> 1); ci = j & 1; nch = 2; }
    else if (u < 96) { int j = u - 48; qt = 32 + j / 3;    ci = j % 3; nch = 3; }
    else             { int j = u - 96; qt = 48 + (j >> 2); ci = j & 3; nch = 4; }

    const int q0 = qt * 64;
    const int t0 = ci * NCHUNK;
    const int t1 = min(t0 + NCHUNK, qt + 1);

    const int tid = threadIdx.x;
    const int wid = tid >> 5;
    const int lane = tid & 31;
    const int gid = lane >> 2;
    const int tig = lane & 3;
    const int lc = tid & 15;
    const int lr = tid >> 4;

    const float* __restrict__ qbase = g_q + (size_t)b * Tt * Hh;
    const float* __restrict__ kbase = g_k + (size_t)b * Tt * Hh;
    const float* __restrict__ vbase = g_v + (size_t)b * Tt * Hh;

    const uint32_t sbase = (uint32_t)__cvta_generic_to_shared(smu);

    auto load_tile = [&](int t, int s) {
        const int k0 = t * 64;
        const uint32_t ks = sbase + (uint32_t)(s * ASTG) * 4u;
        const uint32_t vs = ks + 64u * KVPAD * 4u;
        #pragma unroll
        for (int p = 0; p < 8; p++) {
            const int row = p * 8 + lr;
            const uint32_t off = (uint32_t)(row * KVPAD + lc * 4) * 4u;
            cpa16(ks + off, &kbase[(size_t)(k0 + row) * Hh + lc * 4]);
            cpa16(vs + off, &vbase[(size_t)(k0 + row) * Hh + lc * 4]);
        }
    };

    const int qr0 = q0 + wid * 16 + gid;
    uint32_t qa[8][4];
    #pragma unroll
    for (int s8 = 0; s8 < 8; s8++) {
        qa[s8][0] = f2tf(qbase[(size_t)(qr0    ) * Hh + s8 * 8 + tig    ]);
        qa[s8][1] = f2tf(qbase[(size_t)(qr0 + 8) * Hh + s8 * 8 + tig    ]);
        qa[s8][2] = f2tf(qbase[(size_t)(qr0    ) * Hh + s8 * 8 + tig + 4]);
        qa[s8][3] = f2tf(qbase[(size_t)(qr0 + 8) * Hh + s8 * 8 + tig + 4]);
    }

    float o[8][4];
    #pragma unroll
    for (int nt = 0; nt < 8; nt++)
        #pragma unroll
        for (int j = 0; j < 4; j++) o[nt][j] = 0.f;
    float m0r = -1e30f, m1r = -1e30f, l0 = 0.f, l1 = 0.f;

    load_tile(t0, 0);
    CP_COMMIT();

    for (int t = t0; t < t1; t++) {
        const int k0 = t * 64;
        const int cur = (t - t0) & 1;
        CP_WAIT0();
        __syncthreads();                  // raw tile t landed; prev compute done
        if (t + 1 < t1) { load_tile(t + 1, cur ^ 1); CP_COMMIT(); }

        // In-place f32 -> tf32 convert (cvt off the mma operand path)
        float* stg = smu + cur * ASTG;
        #pragma unroll
        for (int i = 0; i < 17; i++) {
            float* p4 = &stg[(i * 128 + tid) * 4];
            float4 vq = *(float4*)p4;
            uint32_t* d = (uint32_t*)p4;
            d[0] = f2tf(vq.x); d[1] = f2tf(vq.y); d[2] = f2tf(vq.z); d[3] = f2tf(vq.w);
        }
        __syncthreads();

        const uint32_t* Kf = (const uint32_t*)stg;
        const uint32_t* Vf = Kf + 64 * KVPAD;

        // bias prefetch (scaled into log2 domain; LDGs overlap mma loop)
        float2 bz0[8], bz1[8];
        #pragma unroll
        for (int nt = 0; nt < 8; nt++) {
            const int c0 = k0 + nt * 8 + tig * 2;
            bz0[nt] = *(const float2*)&bias[(size_t)(qr0    ) * Tt + c0];
            bz1[nt] = *(const float2*)&bias[(size_t)(qr0 + 8) * Tt + c0];
        }

        // --- S = Q K^T ---
        float s[8][4];
        #pragma unroll
        for (int nt = 0; nt < 8; nt++) {
            #pragma unroll
            for (int j = 0; j < 4; j++) s[nt][j] = 0.f;
            const uint32_t* krow = &Kf[(nt * 8 + gid) * KVPAD];
            #pragma unroll
            for (int s8 = 0; s8 < 8; s8++) {
                uint32_t b0 = krow[s8 * 8 + tig    ];
                uint32_t b1 = krow[s8 * 8 + tig + 4];
                mma_tf32(s[nt], qa[s8], b0, b1);
            }
        }

        // --- bias (log2 domain) + causal mask ---
        const bool diag = (t == qt);
        #pragma unroll
        for (int nt = 0; nt < 8; nt++) {
            const int c0 = k0 + nt * 8 + tig * 2;
            s[nt][0] += bz0[nt].x * LOG2E; s[nt][1] += bz0[nt].y * LOG2E;
            s[nt][2] += bz1[nt].x * LOG2E; s[nt][3] += bz1[nt].y * LOG2E;
            if (diag) {
                if (c0     > qr0    ) s[nt][0] = -1e30f;
                if (c0 + 1 > qr0    ) s[nt][1] = -1e30f;
                if (c0     > qr0 + 8) s[nt][2] = -1e30f;
                if (c0 + 1 > qr0 + 8) s[nt][3] = -1e30f;
            }
        }

        // --- online softmax (base-2) ---
        float mx0 = -1e30f, mx1 = -1e30f;
        #pragma unroll
        for (int nt = 0; nt < 8; nt++) {
            mx0 = fmaxf(mx0, fmaxf(s[nt][0], s[nt][1]));
            mx1 = fmaxf(mx1, fmaxf(s[nt][2], s[nt][3]));
        }
        mx0 = fmaxf(mx0, __shfl_xor_sync(0xffffffffu, mx0, 1));
        mx0 = fmaxf(mx0, __shfl_xor_sync(0xffffffffu, mx0, 2));
        mx1 = fmaxf(mx1, __shfl_xor_sync(0xffffffffu, mx1, 1));
        mx1 = fmaxf(mx1, __shfl_xor_sync(0xffffffffu, mx1, 2));

        const float mn0 = fmaxf(m0r, mx0);
        const float mn1 = fmaxf(m1r, mx1);
        const float cr0 = ex2(m0r - mn0);
        const float cr1 = ex2(m1r - mn1);
        m0r = mn0; m1r = mn1;

        float rs0 = 0.f, rs1 = 0.f;
        #pragma unroll
        for (int nt = 0; nt < 8; nt++) {
            s[nt][0] = ex2(s[nt][0] - mn0);
            s[nt][1] = ex2(s[nt][1] - mn0);
            s[nt][2] = ex2(s[nt][2] - mn1);
            s[nt][3] = ex2(s[nt][3] - mn1);
            rs0 += s[nt][0] + s[nt][1];
            rs1 += s[nt][2] + s[nt][3];
        }
        rs0 += __shfl_xor_sync(0xffffffffu, rs0, 1);
        rs0 += __shfl_xor_sync(0xffffffffu, rs0, 2);
        rs1 += __shfl_xor_sync(0xffffffffu, rs1, 1);
        rs1 += __shfl_xor_sync(0xffffffffu, rs1, 2);
        l0 = l0 * cr0 + rs0;
        l1 = l1 * cr1 + rs1;

        #pragma unroll
        for (int nt = 0; nt < 8; nt++) {
            o[nt][0] *= cr0; o[nt][1] *= cr0;
            o[nt][2] *= cr1; o[nt][3] *= cr1;
        }

        // --- O += P V --- (P from accumulator; V rows 8c+2tig, 8c+2tig+1)
        #pragma unroll
        for (int c8 = 0; c8 < 8; c8++) {
            uint32_t pa[4];
            pa[0] = f2tf(s[c8][0]);
            pa[1] = f2tf(s[c8][2]);
            pa[2] = f2tf(s[c8][1]);
            pa[3] = f2tf(s[c8][3]);
            const uint32_t* vrow0 = &Vf[(c8 * 8 + 2 * tig    ) * KVPAD];
            const uint32_t* vrow1 = &Vf[(c8 * 8 + 2 * tig + 1) * KVPAD];
            #pragma unroll
            for (int nt = 0; nt < 8; nt++) {
                uint32_t b0 = vrow0[nt * 8 + gid];
                uint32_t b1 = vrow1[nt * 8 + gid];
                mma_tf32(o[nt], pa, b0, b1);
            }
        }
        // no trailing barrier: next iteration's top barrier orders reuse
    }

    if (nch == 1) {
        const float inv0 = 1.0f / l0;
        const float inv1 = 1.0f / l1;
        float* orow0 = &outp[((size_t)b * Tt + qr0    ) * Hh];
        float* orow1 = &outp[((size_t)b * Tt + qr0 + 8) * Hh];
        #pragma unroll
        for (int nt = 0; nt < 8; nt++) {
            *(float2*)&orow0[nt * 8 + tig * 2] =
                make_float2(o[nt][0] * inv0, o[nt][1] * inv0);
            *(float2*)&orow1[nt * 8 + tig * 2] =
                make_float2(o[nt][2] * inv1, o[nt][3] * inv1);
        }
    } else {
        const int slot = (b * 64 + qt) * 4 + ci;
        const int r0 = wid * 16 + gid;
        float* prow0 = g_pO[slot][r0];
        float* prow1 = g_pO[slot][r0 + 8];
        #pragma unroll
        for (int nt = 0; nt < 8; nt++) {
            *(float2*)&prow0[nt * 8 + tig * 2] = make_float2(o[nt][0], o[nt][1]);
            *(float2*)&prow1[nt * 8 + tig * 2] = make_float2(o[nt][2], o[nt][3]);
        }
        if (tig == 0) {
            g_pml[slot][r0    ] = make_float2(m0r, l0);
            g_pml[slot][r0 + 8] = make_float2(m1r, l1);
        }
    }
}

// ---------------------------------------------------------------------------
// Kernel 3: merge split-K partials for qt >= 16 (log2-domain m).
// ---------------------------------------------------------------------------
__global__ __launch_bounds__(256) void reduce_kernel(float* __restrict__ outp)
{
    const int b  = blockIdx.x / 48;
    const int qt = 16 + blockIdx.x % 48;
    const int nch = (qt >> 4) + 1;
    const int row = threadIdx.x >> 2;
    const int seg = threadIdx.x & 3;
    const int slot0 = (b * 64 + qt) * 4;

    float m[4], w[4];
    float M = -1e30f;
    #pragma unroll
    for (int i = 0; i < 4; i++) {
        if (i < nch) { m[i] = g_pml[slot0 + i][row].x; M = fmaxf(M, m[i]); }
    }
    float L = 0.f;
    #pragma unroll
    for (int i = 0; i < 4; i++) {
        if (i < nch) {
            w[i] = ex2(m[i] - M);
            L += w[i] * g_pml[slot0 + i][row].y;
        }
    }
    const float inv = 1.0f / L;

    float* orow = &outp[((size_t)b * Tt + qt * 64 + row) * Hh + seg * 16];
    #pragma unroll
    for (int g4 = 0; g4 < 4; g4++) {
        float4 acc = make_float4(0.f, 0.f, 0.f, 0.f);
        #pragma unroll
        for (int i = 0; i < 4; i++) {
            if (i < nch) {
                float4 pv = *(const float4*)&g_pO[slot0 + i][row][seg * 16 + g4 * 4];
                acc.x += w[i] * pv.x; acc.y += w[i] * pv.y;
                acc.z += w[i] * pv.z; acc.w += w[i] * pv.w;
            }
        }
        acc.x *= inv; acc.y *= inv; acc.z *= inv; acc.w *= inv;
        *(float4*)&orow[g4 * 4] = acc;
    }
}

// ---------------------------------------------------------------------------
extern "C" void kernel_launch(void* const* d_in, const int* in_sizes, int n_in,
                              void* d_out, int out_size)
{
    const float* x    = (const float*)d_in[0];
    const float* bias = (const float*)d_in[1];
    const float* wk   = (const float*)d_in[2];
    const float* wq   = (const float*)d_in[3];
    const float* wv   = (const float*)d_in[4];
    float* out = (float*)d_out;

    const int psmem = (64 * KPAD + 64 * WPAD) * 4;   // 68608 B
    cudaFuncSetAttribute(proj_kernel,
                         cudaFuncAttributeMaxDynamicSharedMemorySize, psmem);
    proj_kernel<<<Bb * Tt / 64, 128, psmem>>>(x, wk, wq, wv);

    const int asmem = 2 * (2 * 64 * KVPAD) * 4;      // 69632 B
    cudaFuncSetAttribute(attn_kernel,
                         cudaFuncAttributeMaxDynamicSharedMemorySize, asmem);
    attn_kernel<<<640, 128, asmem>>>(bias, out);

    reduce_kernel<<<Bb * 48, 256>>>(out);
}

// round 9
// speedup vs baseline: 1.1619x; 1.1619x over previous
#include <cuda_runtime.h>
#include <cuda_bf16.h>
#include <cstdint>

// Problem constants
#define Bb 4
#define Tt 4096
#define Cc 1024
#define Hh 64
#define KPAD 68    // proj X / attn K smem stride (words)
#define VPAD 72    // attn V smem stride (words)
#define WPAD 200   // proj W smem stride (words)
#define NCHUNK 8   // attn key-tiles per split chunk (512 keys)
#define LOG2E 1.44269504088896f

// Scratch for projected q/k/v (4 MB each)
__device__ float g_q[Bb * Tt * Hh];
__device__ float g_k[Bb * Tt * Hh];
__device__ float g_v[Bb * Tt * Hh];

// Split-K partials: slot = ((b*64+qt)*8 + ci)
__device__ float  g_pO[Bb * 64 * 8][64][Hh];     // 32 MB
__device__ float2 g_pml[Bb * 64 * 8][64];        // (m_log2, l)

__device__ __forceinline__ uint32_t f2tf(float f) {
    uint32_t u; asm("cvt.rna.tf32.f32 %0, %1;" : "=r"(u) : "f"(f)); return u;
}
__device__ __forceinline__ float ex2(float f) {
    float r; asm("ex2.approx.f32 %0, %1;" : "=f"(r) : "f"(f)); return r;
}

__device__ __forceinline__ void mma_tf32(float* d, const uint32_t* a,
                                         uint32_t b0, uint32_t b1) {
    asm volatile(
        "mma.sync.aligned.m16n8k8.row.col.f32.tf32.tf32.f32 "
        "{%0,%1,%2,%3}, {%4,%5,%6,%7}, {%8,%9}, {%0,%1,%2,%3};"
        : "+f"(d[0]), "+f"(d[1]), "+f"(d[2]), "+f"(d[3])
        : "r"(a[0]), "r"(a[1]), "r"(a[2]), "r"(a[3]), "r"(b0), "r"(b1));
}

// ---------------------------------------------------------------------------
// Kernel 1: fused QKV projection via tf32 mma (measured 58.5us — unchanged
// except q scale now folds log2(e) for base-2 softmax downstream).
// ---------------------------------------------------------------------------
__global__ __launch_bounds__(128, 3) void proj_kernel(
    const float* __restrict__ x,
    const float* __restrict__ wk,
    const float* __restrict__ wq,
    const float* __restrict__ wv)
{
    extern __shared__ uint32_t smp[];
    uint32_t* Xs = smp;                 // [m][c] tf32, stride KPAD
    uint32_t* Ws = smp + 64 * KPAD;     // [c][z*64+h] tf32, stride WPAD

    const int m0 = blockIdx.x * 64;
    const int tid = threadIdx.x;
    const int wid = tid >> 5;
    const int lane = tid & 31;
    const int gid = lane >> 2;
    const int tig = lane & 3;
    const int lc = tid & 15;
    const int lr = tid >> 4;

    float o[6][4][4];
    #pragma unroll
    for (int nt = 0; nt < 6; nt++)
        #pragma unroll
        for (int rb = 0; rb < 4; rb++)
            #pragma unroll
            for (int j = 0; j < 4; j++) o[nt][rb][j] = 0.f;

    for (int k0 = 0; k0 < Cc; k0 += 64) {
        #pragma unroll
        for (int p = 0; p < 8; p++) {
            const int row = p * 8 + lr;
            float4 xv = *(const float4*)&x[(size_t)(m0 + row) * Cc + k0 + lc * 4];
            uint32_t* xd = &Xs[row * KPAD + lc * 4];
            xd[0] = f2tf(xv.x); xd[1] = f2tf(xv.y); xd[2] = f2tf(xv.z); xd[3] = f2tf(xv.w);
        }
        #pragma unroll
        for (int z = 0; z < 3; z++) {
            const float* __restrict__ w = (z == 0) ? wk : ((z == 1) ? wq : wv);
            #pragma unroll
            for (int p = 0; p < 8; p++) {
                const int row = p * 8 + lr;
                float4 wv4 = *(const float4*)&w[(size_t)(k0 + row) * Hh + lc * 4];
                uint32_t* wd = &Ws[row * WPAD + z * 64 + lc * 4];
                wd[0] = f2tf(wv4.x); wd[1] = f2tf(wv4.y); wd[2] = f2tf(wv4.z); wd[3] = f2tf(wv4.w);
            }
        }
        __syncthreads();

        #pragma unroll
        for (int s8 = 0; s8 < 8; s8++) {
            uint32_t a[4][4];
            #pragma unroll
            for (int rb = 0; rb < 4; rb++) {
                const int ar = rb * 16 + gid;
                a[rb][0] = Xs[(ar    ) * KPAD + s8 * 8 + tig    ];
                a[rb][1] = Xs[(ar + 8) * KPAD + s8 * 8 + tig    ];
                a[rb][2] = Xs[(ar    ) * KPAD + s8 * 8 + tig + 4];
                a[rb][3] = Xs[(ar + 8) * KPAD + s8 * 8 + tig + 4];
            }
            #pragma unroll
            for (int nt = 0; nt < 6; nt++) {
                const int ntp = wid * 6 + nt;
                uint32_t b0 = Ws[(s8 * 8 + tig    ) * WPAD + ntp * 8 + gid];
                uint32_t b1 = Ws[(s8 * 8 + tig + 4) * WPAD + ntp * 8 + gid];
                #pragma unroll
                for (int rb = 0; rb < 4; rb++)
                    mma_tf32(o[nt][rb], a[rb], b0, b1);
            }
        }
        __syncthreads();
    }

    #pragma unroll
    for (int nt = 0; nt < 6; nt++) {
        const int ntp = wid * 6 + nt;
        const int z = ntp >> 3;
        float* __restrict__ outp = (z == 0) ? g_k : ((z == 1) ? g_q : g_v);
        const float scale = (z == 1) ? (0.125f * LOG2E) : 1.0f;
        const int hc = (ntp & 7) * 8 + tig * 2;
        #pragma unroll
        for (int rb = 0; rb < 4; rb++) {
            const int mr = m0 + rb * 16 + gid;
            *(float2*)&outp[(size_t)(mr    ) * Hh + hc] =
                make_float2(o[nt][rb][0] * scale, o[nt][rb][1] * scale);
            *(float2*)&outp[(size_t)(mr + 8) * Hh + hc] =
                make_float2(o[nt][rb][2] * scale, o[nt][rb][3] * scale);
        }
    }
}

// ---------------------------------------------------------------------------
// Kernel 2: split-K causal flash attention (R5 inner loop: sync LDG->cvt->STS,
// V slot-permuted, P from accumulator).  NCHUNK=8 fine-grained scheduling.
// Unit decode: u in [0,288); ci from off(ci)=68ci-4ci^2; qt = 8ci + rem.
// ---------------------------------------------------------------------------
__global__ __launch_bounds__(128, 3) void attn_kernel(
    const float* __restrict__ bias,
    float* __restrict__ outp)
{
    extern __shared__ uint32_t smu[];
    uint32_t* Ks = smu;                 // [key][h] tf32, stride KPAD
    uint32_t* Vs = smu + 64 * KPAD;     // [slot][h] tf32, stride VPAD (permuted)

    const int b = blockIdx.x & 3;
    const int u = blockIdx.x >> 2;      // 0..287
    int ci = 0;
    #pragma unroll
    for (int c = 7; c >= 1; c--) {
        if (u >= 68 * c - 4 * c * c) { ci = c; break; }
    }
    const int qt = 8 * ci + (u - (68 * ci - 4 * ci * ci));
    const int nch = (qt >> 3) + 1;

    const int q0 = qt * 64;
    const int t0 = ci * NCHUNK;
    const int t1 = min(t0 + NCHUNK, qt + 1);

    const int tid = threadIdx.x;
    const int wid = tid >> 5;
    const int lane = tid & 31;
    const int gid = lane >> 2;
    const int tig = lane & 3;
    const int lc = tid & 15;
    const int lr = tid >> 4;

    const float* __restrict__ qbase = g_q + (size_t)b * Tt * Hh;
    const float* __restrict__ kbase = g_k + (size_t)b * Tt * Hh;
    const float* __restrict__ vbase = g_v + (size_t)b * Tt * Hh;

    const int qr0 = q0 + wid * 16 + gid;
    uint32_t qa[8][4];
    #pragma unroll
    for (int s8 = 0; s8 < 8; s8++) {
        qa[s8][0] = f2tf(qbase[(size_t)(qr0    ) * Hh + s8 * 8 + tig    ]);
        qa[s8][1] = f2tf(qbase[(size_t)(qr0 + 8) * Hh + s8 * 8 + tig    ]);
        qa[s8][2] = f2tf(qbase[(size_t)(qr0    ) * Hh + s8 * 8 + tig + 4]);
        qa[s8][3] = f2tf(qbase[(size_t)(qr0 + 8) * Hh + s8 * 8 + tig + 4]);
    }

    float o[8][4];
    #pragma unroll
    for (int nt = 0; nt < 8; nt++)
        #pragma unroll
        for (int j = 0; j < 4; j++) o[nt][j] = 0.f;
    float m0r = -1e30f, m1r = -1e30f, l0 = 0.f, l1 = 0.f;

    for (int t = t0; t < t1; t++) {
        const int k0 = t * 64;

        // Load K (plain) and V (slot-permuted rows), cvt at store.
        #pragma unroll
        for (int p = 0; p < 8; p++) {
            const int row = p * 8 + lr;
            const int r7 = row & 7;
            const int srow = (row & ~7) | ((r7 & 1) ? ((r7 >> 1) + 4) : (r7 >> 1));
            float4 kv = *(const float4*)&kbase[(size_t)(k0 + row) * Hh + lc * 4];
            float4 vv = *(const float4*)&vbase[(size_t)(k0 + row) * Hh + lc * 4];
            uint32_t* kd = &Ks[row * KPAD + lc * 4];
            kd[0] = f2tf(kv.x); kd[1] = f2tf(kv.y); kd[2] = f2tf(kv.z); kd[3] = f2tf(kv.w);
            uint32_t* vd = &Vs[srow * VPAD + lc * 4];
            vd[0] = f2tf(vv.x); vd[1] = f2tf(vv.y); vd[2] = f2tf(vv.z); vd[3] = f2tf(vv.w);
        }
        __syncthreads();

        // --- S = Q K^T ---
        float s[8][4];
        #pragma unroll
        for (int nt = 0; nt < 8; nt++) {
            #pragma unroll
            for (int j = 0; j < 4; j++) s[nt][j] = 0.f;
            const uint32_t* krow = &Ks[(nt * 8 + gid) * KPAD];
            #pragma unroll
            for (int s8 = 0; s8 < 8; s8++) {
                uint32_t b0 = krow[s8 * 8 + tig    ];
                uint32_t b1 = krow[s8 * 8 + tig + 4];
                mma_tf32(s[nt], qa[s8], b0, b1);
            }
        }

        // --- bias (log2 domain) + causal mask ---
        const bool diag = (t == qt);
        #pragma unroll
        for (int nt = 0; nt < 8; nt++) {
            const int c0 = k0 + nt * 8 + tig * 2;
            float2 bz0 = *(const float2*)&bias[(size_t)(qr0    ) * Tt + c0];
            float2 bz1 = *(const float2*)&bias[(size_t)(qr0 + 8) * Tt + c0];
            s[nt][0] += bz0.x * LOG2E; s[nt][1] += bz0.y * LOG2E;
            s[nt][2] += bz1.x * LOG2E; s[nt][3] += bz1.y * LOG2E;
            if (diag) {
                if (c0     > qr0    ) s[nt][0] = -1e30f;
                if (c0 + 1 > qr0    ) s[nt][1] = -1e30f;
                if (c0     > qr0 + 8) s[nt][2] = -1e30f;
                if (c0 + 1 > qr0 + 8) s[nt][3] = -1e30f;
            }
        }

        // --- online softmax (base-2) ---
        float mx0 = -1e30f, mx1 = -1e30f;
        #pragma unroll
        for (int nt = 0; nt < 8; nt++) {
            mx0 = fmaxf(mx0, fmaxf(s[nt][0], s[nt][1]));
            mx1 = fmaxf(mx1, fmaxf(s[nt][2], s[nt][3]));
        }
        mx0 = fmaxf(mx0, __shfl_xor_sync(0xffffffffu, mx0, 1));
        mx0 = fmaxf(mx0, __shfl_xor_sync(0xffffffffu, mx0, 2));
        mx1 = fmaxf(mx1, __shfl_xor_sync(0xffffffffu, mx1, 1));
        mx1 = fmaxf(mx1, __shfl_xor_sync(0xffffffffu, mx1, 2));

        const float mn0 = fmaxf(m0r, mx0);
        const float mn1 = fmaxf(m1r, mx1);
        const float cr0 = ex2(m0r - mn0);
        const float cr1 = ex2(m1r - mn1);
        m0r = mn0; m1r = mn1;

        float rs0 = 0.f, rs1 = 0.f;
        #pragma unroll
        for (int nt = 0; nt < 8; nt++) {
            s[nt][0] = ex2(s[nt][0] - mn0);
            s[nt][1] = ex2(s[nt][1] - mn0);
            s[nt][2] = ex2(s[nt][2] - mn1);
            s[nt][3] = ex2(s[nt][3] - mn1);
            rs0 += s[nt][0] + s[nt][1];
            rs1 += s[nt][2] + s[nt][3];
        }
        rs0 += __shfl_xor_sync(0xffffffffu, rs0, 1);
        rs0 += __shfl_xor_sync(0xffffffffu, rs0, 2);
        rs1 += __shfl_xor_sync(0xffffffffu, rs1, 1);
        rs1 += __shfl_xor_sync(0xffffffffu, rs1, 2);
        l0 = l0 * cr0 + rs0;
        l1 = l1 * cr1 + rs1;

        #pragma unroll
        for (int nt = 0; nt < 8; nt++) {
            o[nt][0] *= cr0; o[nt][1] *= cr0;
            o[nt][2] *= cr1; o[nt][3] *= cr1;
        }

        // --- O += P V (P from accumulator; V rows slot-permuted) ---
        #pragma unroll
        for (int c8 = 0; c8 < 8; c8++) {
            uint32_t pa[4];
            pa[0] = f2tf(s[c8][0]);
            pa[1] = f2tf(s[c8][2]);
            pa[2] = f2tf(s[c8][1]);
            pa[3] = f2tf(s[c8][3]);
            const uint32_t* vrow0 = &Vs[(c8 * 8 + tig    ) * VPAD];
            const uint32_t* vrow1 = &Vs[(c8 * 8 + tig + 4) * VPAD];
            #pragma unroll
            for (int nt = 0; nt < 8; nt++) {
                uint32_t b0 = vrow0[nt * 8 + gid];
                uint32_t b1 = vrow1[nt * 8 + gid];
                mma_tf32(o[nt], pa, b0, b1);
            }
        }
        __syncthreads();
    }

    if (nch == 1) {
        const float inv0 = 1.0f / l0;
        const float inv1 = 1.0f / l1;
        float* orow0 = &outp[((size_t)b * Tt + qr0    ) * Hh];
        float* orow1 = &outp[((size_t)b * Tt + qr0 + 8) * Hh];
        #pragma unroll
        for (int nt = 0; nt < 8; nt++) {
            *(float2*)&orow0[nt * 8 + tig * 2] =
                make_float2(o[nt][0] * inv0, o[nt][1] * inv0);
            *(float2*)&orow1[nt * 8 + tig * 2] =
                make_float2(o[nt][2] * inv1, o[nt][3] * inv1);
        }
    } else {
        const int slot = (b * 64 + qt) * 8 + ci;
        const int r0 = wid * 16 + gid;
        float* prow0 = g_pO[slot][r0];
        float* prow1 = g_pO[slot][r0 + 8];
        #pragma unroll
        for (int nt = 0; nt < 8; nt++) {
            *(float2*)&prow0[nt * 8 + tig * 2] = make_float2(o[nt][0], o[nt][1]);
            *(float2*)&prow1[nt * 8 + tig * 2] = make_float2(o[nt][2], o[nt][3]);
        }
        if (tig == 0) {
            g_pml[slot][r0    ] = make_float2(m0r, l0);
            g_pml[slot][r0 + 8] = make_float2(m1r, l1);
        }
    }
}

// ---------------------------------------------------------------------------
// Kernel 3: merge split-K partials for qt >= 8 (up to 8 chunks, log2-domain m).
// Grid: 4 * 56 CTAs, 256 threads.  Thread: (row = tid>>2, h-seg = tid&3).
// ---------------------------------------------------------------------------
__global__ __launch_bounds__(256) void reduce_kernel(float* __restrict__ outp)
{
    const int b  = blockIdx.x / 56;
    const int qt = 8 + blockIdx.x % 56;
    const int nch = (qt >> 3) + 1;        // 2..8
    const int row = threadIdx.x >> 2;
    const int seg = threadIdx.x & 3;
    const int slot0 = (b * 64 + qt) * 8;

    float m[8], w[8];
    float M = -1e30f;
    #pragma unroll
    for (int i = 0; i < 8; i++) {
        if (i < nch) { m[i] = g_pml[slot0 + i][row].x; M = fmaxf(M, m[i]); }
    }
    float L = 0.f;
    #pragma unroll
    for (int i = 0; i < 8; i++) {
        if (i < nch) {
            w[i] = ex2(m[i] - M);
            L += w[i] * g_pml[slot0 + i][row].y;
        }
    }
    const float inv = 1.0f / L;

    float* orow = &outp[((size_t)b * Tt + qt * 64 + row) * Hh + seg * 16];
    #pragma unroll
    for (int g4 = 0; g4 < 4; g4++) {
        float4 acc = make_float4(0.f, 0.f, 0.f, 0.f);
        #pragma unroll
        for (int i = 0; i < 8; i++) {
            if (i < nch) {
                float4 pv = *(const float4*)&g_pO[slot0 + i][row][seg * 16 + g4 * 4];
                acc.x += w[i] * pv.x; acc.y += w[i] * pv.y;
                acc.z += w[i] * pv.z; acc.w += w[i] * pv.w;
            }
        }
        acc.x *= inv; acc.y *= inv; acc.z *= inv; acc.w *= inv;
        *(float4*)&orow[g4 * 4] = acc;
    }
}

// ---------------------------------------------------------------------------
extern "C" void kernel_launch(void* const* d_in, const int* in_sizes, int n_in,
                              void* d_out, int out_size)
{
    const float* x    = (const float*)d_in[0];
    const float* bias = (const float*)d_in[1];
    const float* wk   = (const float*)d_in[2];
    const float* wq   = (const float*)d_in[3];
    const float* wv   = (const float*)d_in[4];
    float* out = (float*)d_out;

    const int psmem = (64 * KPAD + 64 * WPAD) * 4;   // 68608 B
    cudaFuncSetAttribute(proj_kernel,
                         cudaFuncAttributeMaxDynamicSharedMemorySize, psmem);
    proj_kernel<<<Bb * Tt / 64, 128, psmem>>>(x, wk, wq, wv);

    const int asmem = (64 * KPAD + 64 * VPAD) * 4;   // 35840 B
    cudaFuncSetAttribute(attn_kernel,
                         cudaFuncAttributeMaxDynamicSharedMemorySize, asmem);
    attn_kernel<<<4 * 288, 128, asmem>>>(bias, out);

    reduce_kernel<<<Bb * 56, 256>>>(out);
}